// round 1
// baseline (speedup 1.0000x reference)
#include <cuda_runtime.h>
#include <cstdint>

#define N_NODES 50000
#define N_EDGES 800000
#define D 64
#define N_GRAPHS 512
#define N_LAYERS 3
#define HID_FC 64
#define N_CLASSES 10

// Scratch (device globals: no allocations allowed)
__device__ float g_h[N_NODES * D];
__device__ float g_agg[N_NODES * D];
__device__ unsigned int g_pool[N_GRAPHS * D];

// ---------------------------------------------------------------------------
// agg = h  (GIN self term, eps = 0)
// ---------------------------------------------------------------------------
__global__ void copy_kernel(const float4* __restrict__ src, float4* __restrict__ dst, int n4) {
    int i = blockIdx.x * blockDim.x + threadIdx.x;
    if (i < n4) dst[i] = src[i];
}

// ---------------------------------------------------------------------------
// agg[dst] += h[src] over all edges. 16 threads per edge, float4 per thread.
// ---------------------------------------------------------------------------
__global__ void scatter_kernel(const float* __restrict__ hin,
                               const int* __restrict__ src,
                               const int* __restrict__ dst) {
    unsigned int gid = blockIdx.x * 256u + threadIdx.x;
    unsigned int e = gid >> 4;
    unsigned int lane = gid & 15u;
    if (e >= N_EDGES) return;
    int s = src[e];
    int d = dst[e];
    float4 v = reinterpret_cast<const float4*>(hin)[(size_t)s * 16 + lane];
    float* base = g_agg + (size_t)d * D + lane * 4;
    atomicAdd(base + 0, v.x);
    atomicAdd(base + 1, v.y);
    atomicAdd(base + 2, v.z);
    atomicAdd(base + 3, v.w);
}

// ---------------------------------------------------------------------------
// h = relu(agg @ W1 + b1) @ W2 + b2   (fused per-layer MLP)
// One thread per node row; W1/W2 staged in smem; register accumulators.
// ---------------------------------------------------------------------------
__global__ __launch_bounds__(128) void mlp_kernel(const float* __restrict__ xin,
                                                  const float* __restrict__ W1,
                                                  const float* __restrict__ b1,
                                                  const float* __restrict__ W2,
                                                  const float* __restrict__ b2,
                                                  float* __restrict__ hout) {
    __shared__ float W1s[D * D];
    __shared__ float W2s[D * D];
    __shared__ float b1s[D];
    __shared__ float b2s[D];

    int tid = threadIdx.x;
    for (int i = tid; i < D * D; i += 128) {
        W1s[i] = W1[i];
        W2s[i] = W2[i];
    }
    if (tid < D) {
        b1s[tid] = b1[tid];
        b2s[tid] = b2[tid];
    }
    __syncthreads();

    int row = blockIdx.x * 128 + tid;
    bool valid = (row < N_NODES);

    // ---- GEMM 1: t = relu(x @ W1 + b1) ----
    float t[D];
#pragma unroll
    for (int j = 0; j < D; j++) t[j] = b1s[j];

    if (valid) {
        const float4* x4 = reinterpret_cast<const float4*>(xin + (size_t)row * D);
#pragma unroll
        for (int k4 = 0; k4 < D / 4; k4++) {
            float4 xv = x4[k4];
            float xk[4] = {xv.x, xv.y, xv.z, xv.w};
#pragma unroll
            for (int kk = 0; kk < 4; kk++) {
                float xs = xk[kk];
                const float4* wrow = reinterpret_cast<const float4*>(W1s + (k4 * 4 + kk) * D);
#pragma unroll
                for (int j4 = 0; j4 < D / 4; j4++) {
                    float4 w = wrow[j4];
                    t[j4 * 4 + 0] += xs * w.x;
                    t[j4 * 4 + 1] += xs * w.y;
                    t[j4 * 4 + 2] += xs * w.z;
                    t[j4 * 4 + 3] += xs * w.w;
                }
            }
        }
    }
#pragma unroll
    for (int j = 0; j < D; j++) t[j] = fmaxf(t[j], 0.0f);

    // ---- GEMM 2: o = t @ W2 + b2 ----
    float o[D];
#pragma unroll
    for (int j = 0; j < D; j++) o[j] = b2s[j];
#pragma unroll
    for (int k = 0; k < D; k++) {
        float tv = t[k];
        const float4* wrow = reinterpret_cast<const float4*>(W2s + k * D);
#pragma unroll
        for (int j4 = 0; j4 < D / 4; j4++) {
            float4 w = wrow[j4];
            o[j4 * 4 + 0] += tv * w.x;
            o[j4 * 4 + 1] += tv * w.y;
            o[j4 * 4 + 2] += tv * w.z;
            o[j4 * 4 + 3] += tv * w.w;
        }
    }

    if (valid) {
        float4* o4 = reinterpret_cast<float4*>(hout + (size_t)row * D);
#pragma unroll
        for (int j4 = 0; j4 < D / 4; j4++) {
            o4[j4] = make_float4(o[j4 * 4 + 0], o[j4 * 4 + 1], o[j4 * 4 + 2], o[j4 * 4 + 3]);
        }
    }
}

// ---------------------------------------------------------------------------
// Global max pool via monotone unsigned encoding + atomicMax.
// encode(f): top bit 0 -> set top bit; top bit 1 (negative) -> bitwise NOT.
// ---------------------------------------------------------------------------
__global__ void pool_init_kernel() {
    int i = blockIdx.x * blockDim.x + threadIdx.x;
    if (i < N_GRAPHS * D) g_pool[i] = 0x00800000u;  // encode(-FLT_MAX)
}

__global__ void pool_max_kernel(const int* __restrict__ batch) {
    int gid = blockIdx.x * blockDim.x + threadIdx.x;
    if (gid >= N_NODES * D) return;
    int n = gid >> 6;
    int d = gid & 63;
    float v = g_h[(size_t)n * D + d];
    unsigned int bits = __float_as_uint(v);
    unsigned int enc = (bits & 0x80000000u) ? ~bits : (bits | 0x80000000u);
    int g = batch[n];
    atomicMax(&g_pool[(size_t)g * D + d], enc);
}

// ---------------------------------------------------------------------------
// FC head + log_softmax. One block (64 threads) per graph.
// ---------------------------------------------------------------------------
__global__ __launch_bounds__(64) void fc_kernel(const float* __restrict__ fcW1,
                                                const float* __restrict__ fcb1,
                                                const float* __restrict__ fcW2,
                                                const float* __restrict__ fcb2,
                                                float* __restrict__ out) {
    __shared__ float xr[D];
    __shared__ float hid[HID_FC];
    __shared__ float logits[N_CLASSES];
    __shared__ float m_s, lse_s;

    int g = blockIdx.x;
    int t = threadIdx.x;

    unsigned int e = g_pool[(size_t)g * D + t];
    unsigned int u = (e & 0x80000000u) ? (e & 0x7FFFFFFFu) : ~e;
    xr[t] = __uint_as_float(u);
    __syncthreads();

    float a = fcb1[t];
#pragma unroll
    for (int k = 0; k < D; k++) a += xr[k] * fcW1[k * HID_FC + t];
    hid[t] = fmaxf(a, 0.0f);
    __syncthreads();

    if (t < N_CLASSES) {
        float a2 = fcb2[t];
#pragma unroll
        for (int k = 0; k < HID_FC; k++) a2 += hid[k] * fcW2[k * N_CLASSES + t];
        logits[t] = a2;
    }
    __syncthreads();

    if (t == 0) {
        float m = logits[0];
#pragma unroll
        for (int j = 1; j < N_CLASSES; j++) m = fmaxf(m, logits[j]);
        float s = 0.0f;
#pragma unroll
        for (int j = 0; j < N_CLASSES; j++) s += expf(logits[j] - m);
        m_s = m;
        lse_s = logf(s);
    }
    __syncthreads();

    if (t < N_CLASSES) out[(size_t)g * N_CLASSES + t] = logits[t] - m_s - lse_s;
}

// ---------------------------------------------------------------------------
extern "C" void kernel_launch(void* const* d_in, const int* in_sizes, int n_in,
                              void* d_out, int out_size) {
    const float* x      = (const float*)d_in[0];
    const float* convW1 = (const float*)d_in[1];
    const float* convb1 = (const float*)d_in[2];
    const float* convW2 = (const float*)d_in[3];
    const float* convb2 = (const float*)d_in[4];
    const float* fcW1   = (const float*)d_in[5];
    const float* fcb1   = (const float*)d_in[6];
    const float* fcW2   = (const float*)d_in[7];
    const float* fcb2   = (const float*)d_in[8];
    const int* edge_index = (const int*)d_in[9];
    const int* batch      = (const int*)d_in[10];
    float* out = (float*)d_out;

    const int* src = edge_index;
    const int* dst = edge_index + N_EDGES;

    float* h_ptr = nullptr;
    float* agg_ptr = nullptr;
    cudaGetSymbolAddress((void**)&h_ptr, g_h);
    cudaGetSymbolAddress((void**)&agg_ptr, g_agg);

    const int n4 = N_NODES * D / 4;                 // 800000 float4
    const int copy_blocks = (n4 + 255) / 256;
    const int scatter_blocks = (N_EDGES * 16) / 256;  // 50000
    const int mlp_blocks = (N_NODES + 127) / 128;     // 391
    const int poolmax_blocks = (N_NODES * D + 255) / 256;

    for (int l = 0; l < N_LAYERS; l++) {
        const float* hin = (l == 0) ? x : h_ptr;
        copy_kernel<<<copy_blocks, 256>>>((const float4*)hin, (float4*)agg_ptr, n4);
        scatter_kernel<<<scatter_blocks, 256>>>(hin, src, dst);
        mlp_kernel<<<mlp_blocks, 128>>>(agg_ptr,
                                        convW1 + (size_t)l * D * D, convb1 + (size_t)l * D,
                                        convW2 + (size_t)l * D * D, convb2 + (size_t)l * D,
                                        h_ptr);
    }

    pool_init_kernel<<<(N_GRAPHS * D + 255) / 256, 256>>>();
    pool_max_kernel<<<poolmax_blocks, 256>>>(batch);
    fc_kernel<<<N_GRAPHS, 64>>>(fcW1, fcb1, fcW2, fcb2, out);
}

// round 2
// speedup vs baseline: 1.9299x; 1.9299x over previous
#include <cuda_runtime.h>
#include <cstdint>

#define N_NODES 50000
#define N_EDGES 800000
#define D 64
#define N_GRAPHS 512
#define N_LAYERS 3
#define HID_FC 64
#define N_CLASSES 10

// Scratch (device globals: no allocations allowed)
__device__ float g_h[N_NODES * D];
__device__ float g_agg[N_NODES * D];
__device__ unsigned int g_pool[N_GRAPHS * D];

// ---------------------------------------------------------------------------
// agg[dst] += h[src] over all edges. 16 threads per edge, one v4 RED each.
// ---------------------------------------------------------------------------
__global__ void scatter_kernel(const float4* __restrict__ hin4,
                               const int* __restrict__ src,
                               const int* __restrict__ dst,
                               float4* __restrict__ agg4) {
    unsigned int gid = blockIdx.x * 256u + threadIdx.x;
    unsigned int e = gid >> 4;
    unsigned int lane = gid & 15u;
    if (e >= N_EDGES) return;
    int s = src[e];
    int d = dst[e];
    float4 v = hin4[(size_t)s * 16 + lane];
    float4* p = agg4 + (size_t)d * 16 + lane;
    asm volatile("red.global.add.v4.f32 [%0], {%1, %2, %3, %4};"
                 :: "l"(p), "f"(v.x), "f"(v.y), "f"(v.z), "f"(v.w)
                 : "memory");
}

// ---------------------------------------------------------------------------
// in = h[row] + agg[row];  h_out = relu(in @ W1 + b1) @ W2 + b2
// mode 0: write hout, zero agg (prepares next layer's scatter)
// mode 1: last layer — fused global-max-pool (atomicMax into g_pool), no hout
// ---------------------------------------------------------------------------
__global__ __launch_bounds__(128) void mlp_kernel(const float* __restrict__ xin,
                                                  float* __restrict__ agg,
                                                  const float* __restrict__ W1,
                                                  const float* __restrict__ b1,
                                                  const float* __restrict__ W2,
                                                  const float* __restrict__ b2,
                                                  float* __restrict__ hout,
                                                  const int* __restrict__ batch,
                                                  int mode) {
    __shared__ float W1s[D * D];
    __shared__ float W2s[D * D];
    __shared__ float b1s[D];
    __shared__ float b2s[D];

    int tid = threadIdx.x;
    for (int i = tid; i < D * D; i += 128) {
        W1s[i] = W1[i];
        W2s[i] = W2[i];
    }
    if (tid < D) {
        b1s[tid] = b1[tid];
        b2s[tid] = b2[tid];
    }
    __syncthreads();

    int row = blockIdx.x * 128 + tid;
    if (row >= N_NODES) return;

    // ---- GEMM 1: t = relu((x + agg) @ W1 + b1) ----
    float t[D];
#pragma unroll
    for (int j = 0; j < D; j++) t[j] = b1s[j];

    {
        const float4* x4 = reinterpret_cast<const float4*>(xin + (size_t)row * D);
        float4* a4 = reinterpret_cast<float4*>(agg + (size_t)row * D);
#pragma unroll
        for (int k4 = 0; k4 < D / 4; k4++) {
            float4 xv = x4[k4];
            float4 av = a4[k4];
            float xk[4] = {xv.x + av.x, xv.y + av.y, xv.z + av.z, xv.w + av.w};
            if (mode == 0) a4[k4] = make_float4(0.f, 0.f, 0.f, 0.f);
#pragma unroll
            for (int kk = 0; kk < 4; kk++) {
                float xs = xk[kk];
                const float4* wrow = reinterpret_cast<const float4*>(W1s + (k4 * 4 + kk) * D);
#pragma unroll
                for (int j4 = 0; j4 < D / 4; j4++) {
                    float4 w = wrow[j4];
                    t[j4 * 4 + 0] += xs * w.x;
                    t[j4 * 4 + 1] += xs * w.y;
                    t[j4 * 4 + 2] += xs * w.z;
                    t[j4 * 4 + 3] += xs * w.w;
                }
            }
        }
    }
#pragma unroll
    for (int j = 0; j < D; j++) t[j] = fmaxf(t[j], 0.0f);

    // ---- GEMM 2: o = t @ W2 + b2, in 4 chunks of 16 outputs ----
    int g = (mode == 1) ? batch[row] : 0;
    unsigned int* poolrow = g_pool + (size_t)g * D;
    float4* o4 = reinterpret_cast<float4*>(hout + (size_t)row * D);

#pragma unroll
    for (int c = 0; c < 4; c++) {  // chunk of 16 output columns
        float o[16];
#pragma unroll
        for (int j = 0; j < 16; j++) o[j] = b2s[c * 16 + j];
#pragma unroll
        for (int k = 0; k < D; k++) {
            float tv = t[k];
            const float4* wrow = reinterpret_cast<const float4*>(W2s + k * D + c * 16);
#pragma unroll
            for (int j4 = 0; j4 < 4; j4++) {
                float4 w = wrow[j4];
                o[j4 * 4 + 0] += tv * w.x;
                o[j4 * 4 + 1] += tv * w.y;
                o[j4 * 4 + 2] += tv * w.z;
                o[j4 * 4 + 3] += tv * w.w;
            }
        }
        if (mode == 0) {
#pragma unroll
            for (int j4 = 0; j4 < 4; j4++)
                o4[c * 4 + j4] = make_float4(o[j4 * 4 + 0], o[j4 * 4 + 1],
                                             o[j4 * 4 + 2], o[j4 * 4 + 3]);
        } else {
#pragma unroll
            for (int j = 0; j < 16; j++) {
                unsigned int bits = __float_as_uint(o[j]);
                unsigned int enc = (bits & 0x80000000u) ? ~bits : (bits | 0x80000000u);
                atomicMax(&poolrow[c * 16 + j], enc);
            }
        }
    }
}

// ---------------------------------------------------------------------------
__global__ void pool_init_kernel() {
    int i = blockIdx.x * blockDim.x + threadIdx.x;
    if (i < N_GRAPHS * D) g_pool[i] = 0x00800000u;  // encode(-FLT_MAX)
}

// ---------------------------------------------------------------------------
// FC head + log_softmax. One block (64 threads) per graph.
// ---------------------------------------------------------------------------
__global__ __launch_bounds__(64) void fc_kernel(const float* __restrict__ fcW1,
                                                const float* __restrict__ fcb1,
                                                const float* __restrict__ fcW2,
                                                const float* __restrict__ fcb2,
                                                float* __restrict__ out) {
    __shared__ float xr[D];
    __shared__ float hid[HID_FC];
    __shared__ float logits[N_CLASSES];
    __shared__ float m_s, lse_s;

    int g = blockIdx.x;
    int t = threadIdx.x;

    unsigned int e = g_pool[(size_t)g * D + t];
    unsigned int u = (e & 0x80000000u) ? (e & 0x7FFFFFFFu) : ~e;
    xr[t] = __uint_as_float(u);
    __syncthreads();

    float a = fcb1[t];
#pragma unroll
    for (int k = 0; k < D; k++) a += xr[k] * fcW1[k * HID_FC + t];
    hid[t] = fmaxf(a, 0.0f);
    __syncthreads();

    if (t < N_CLASSES) {
        float a2 = fcb2[t];
#pragma unroll
        for (int k = 0; k < HID_FC; k++) a2 += hid[k] * fcW2[k * N_CLASSES + t];
        logits[t] = a2;
    }
    __syncthreads();

    if (t == 0) {
        float m = logits[0];
#pragma unroll
        for (int j = 1; j < N_CLASSES; j++) m = fmaxf(m, logits[j]);
        float s = 0.0f;
#pragma unroll
        for (int j = 0; j < N_CLASSES; j++) s += expf(logits[j] - m);
        m_s = m;
        lse_s = logf(s);
    }
    __syncthreads();

    if (t < N_CLASSES) out[(size_t)g * N_CLASSES + t] = logits[t] - m_s - lse_s;
}

// ---------------------------------------------------------------------------
extern "C" void kernel_launch(void* const* d_in, const int* in_sizes, int n_in,
                              void* d_out, int out_size) {
    const float* x      = (const float*)d_in[0];
    const float* convW1 = (const float*)d_in[1];
    const float* convb1 = (const float*)d_in[2];
    const float* convW2 = (const float*)d_in[3];
    const float* convb2 = (const float*)d_in[4];
    const float* fcW1   = (const float*)d_in[5];
    const float* fcb1   = (const float*)d_in[6];
    const float* fcW2   = (const float*)d_in[7];
    const float* fcb2   = (const float*)d_in[8];
    const int* edge_index = (const int*)d_in[9];
    const int* batch      = (const int*)d_in[10];
    float* out = (float*)d_out;

    const int* src = edge_index;
    const int* dst = edge_index + N_EDGES;

    float* h_ptr = nullptr;
    float* agg_ptr = nullptr;
    cudaGetSymbolAddress((void**)&h_ptr, g_h);
    cudaGetSymbolAddress((void**)&agg_ptr, g_agg);

    const int scatter_blocks = (N_EDGES * 16) / 256;  // 50000
    const int mlp_blocks = (N_NODES + 127) / 128;     // 391

    // agg must be zero at the start of every replay (layer-0/1 MLPs re-zero
    // their rows for the next layer; the last layer doesn't, so the memset
    // inside the graph restores the invariant on each replay).
    cudaMemsetAsync(agg_ptr, 0, (size_t)N_NODES * D * sizeof(float));
    pool_init_kernel<<<(N_GRAPHS * D + 255) / 256, 256>>>();

    for (int l = 0; l < N_LAYERS; l++) {
        const float* hin = (l == 0) ? x : h_ptr;
        int mode = (l == N_LAYERS - 1) ? 1 : 0;
        scatter_kernel<<<scatter_blocks, 256>>>((const float4*)hin, src, dst,
                                                (float4*)agg_ptr);
        mlp_kernel<<<mlp_blocks, 128>>>(hin, agg_ptr,
                                        convW1 + (size_t)l * D * D, convb1 + (size_t)l * D,
                                        convW2 + (size_t)l * D * D, convb2 + (size_t)l * D,
                                        h_ptr, batch, mode);
    }

    fc_kernel<<<N_GRAPHS, 64>>>(fcW1, fcb1, fcW2, fcb2, out);
}